// round 1
// baseline (speedup 1.0000x reference)
#include <cuda_runtime.h>

// penalty = sum_{b,k} S[b,k] * || P[i_b] - P[j_{b,k}] ||_2
// Shapes: P [500000,128] f32, i [4096] i32, j [4096,64] i32, S [4096,64] f32.
// Output: scalar f32.

#define B_TOTAL 4096
#define K_NEIGH 64
#define D_DIM   128
#define NWARPS  8

__global__ void zero_out_kernel(float* out) { *out = 0.0f; }

__global__ __launch_bounds__(NWARPS * 32, 8)
void custom_loss_kernel(const float* __restrict__ P,
                        const int*   __restrict__ i_idx,
                        const int*   __restrict__ j_idx,
                        const float* __restrict__ S,
                        float* __restrict__ out) {
    const int b    = blockIdx.x;
    const int tid  = threadIdx.x;
    const int lane = tid & 31;
    const int w    = tid >> 5;

    __shared__ float4 sPi[D_DIM / 4];     // 128 floats = 32 float4
    __shared__ float  warp_sums[NWARPS];

    // Stage P[i_b] into shared (one warp's worth of float4s)
    if (tid < 32) {
        long long irow = (long long)i_idx[b];
        sPi[tid] = __ldg(reinterpret_cast<const float4*>(P + irow * D_DIM) + tid);
    }
    __syncthreads();

    const float4 pi = sPi[lane];

    float acc = 0.0f;
    #pragma unroll
    for (int k = w; k < K_NEIGH; k += NWARPS) {
        long long jrow = (long long)j_idx[b * K_NEIGH + k];
        float4 pj = __ldg(reinterpret_cast<const float4*>(P + jrow * D_DIM) + lane);
        float dx = pi.x - pj.x;
        float dy = pi.y - pj.y;
        float dz = pi.z - pj.z;
        float dw = pi.w - pj.w;
        float sq = dx * dx + dy * dy + dz * dz + dw * dw;
        // warp tree reduction of the 128-element squared distance
        #pragma unroll
        for (int off = 16; off > 0; off >>= 1)
            sq += __shfl_xor_sync(0xFFFFFFFFu, sq, off);
        if (lane == 0)
            acc += sqrtf(sq) * __ldg(S + b * K_NEIGH + k);
    }

    if (lane == 0) warp_sums[w] = acc;
    __syncthreads();

    if (tid == 0) {
        float s = 0.0f;
        #pragma unroll
        for (int i = 0; i < NWARPS; i++) s += warp_sums[i];
        atomicAdd(out, s);
    }
}

extern "C" void kernel_launch(void* const* d_in, const int* in_sizes, int n_in,
                              void* d_out, int out_size) {
    const float* P  = (const float*)d_in[0];
    const int*   ii = (const int*)  d_in[1];
    const int*   jj = (const int*)  d_in[2];
    const float* S  = (const float*)d_in[3];
    float* out = (float*)d_out;

    zero_out_kernel<<<1, 1>>>(out);
    custom_loss_kernel<<<B_TOTAL, NWARPS * 32>>>(P, ii, jj, S, out);
}

// round 2
// speedup vs baseline: 1.0601x; 1.0601x over previous
#include <cuda_runtime.h>

// penalty = sum_{b,k} S[b,k] * || P[i_b] - P[j_{b,k}] ||_2
// P [500000,128] f32, i [4096] i32, j [4096,64] i32, S [4096,64] f32 -> scalar f32.

#define B_TOTAL 4096
#define K_NEIGH 64
#define D_DIM   128
#define NWARPS  8
#define KPW     (K_NEIGH / NWARPS)   // 8 k-values per warp

__global__ void zero_out_kernel(float* out) { *out = 0.0f; }

__global__ __launch_bounds__(NWARPS * 32, 4)
void custom_loss_kernel(const float* __restrict__ P,
                        const int*   __restrict__ i_idx,
                        const int*   __restrict__ j_idx,
                        const float* __restrict__ S,
                        float* __restrict__ out) {
    const int b    = blockIdx.x;
    const int tid  = threadIdx.x;
    const int lane = tid & 31;
    const int w    = tid >> 5;

    __shared__ int    sJ[K_NEIGH];
    __shared__ float  sS[K_NEIGH];
    __shared__ float4 sPi[D_DIM / 4];
    __shared__ float  warp_sums[NWARPS];

    // Coalesced staging: 64 ints, 64 floats, 32 float4 of P[i_b]
    if (tid < K_NEIGH) {
        sJ[tid] = j_idx[b * K_NEIGH + tid];
    } else if (tid < 2 * K_NEIGH) {
        sS[tid - K_NEIGH] = S[b * K_NEIGH + (tid - K_NEIGH)];
    } else if (tid < 2 * K_NEIGH + 32) {
        long long irow = (long long)i_idx[b];
        int l = tid - 2 * K_NEIGH;
        sPi[l] = __ldg(reinterpret_cast<const float4*>(P + irow * D_DIM) + l);
    }
    __syncthreads();

    const float4 pi = sPi[lane];
    const int kbase = w * KPW;

    // Front-batch all 8 independent gathers (max MLP) before any math.
    float4 pj[KPW];
    #pragma unroll
    for (int m = 0; m < KPW; m++) {
        long long jrow = (long long)sJ[kbase + m];
        pj[m] = __ldg(reinterpret_cast<const float4*>(P + jrow * D_DIM) + lane);
    }

    float acc = 0.0f;
    #pragma unroll
    for (int m = 0; m < KPW; m++) {
        float dx = pi.x - pj[m].x;
        float dy = pi.y - pj[m].y;
        float dz = pi.z - pj[m].z;
        float dw = pi.w - pj[m].w;
        float sq = dx * dx + dy * dy + dz * dz + dw * dw;
        #pragma unroll
        for (int off = 16; off > 0; off >>= 1)
            sq += __shfl_xor_sync(0xFFFFFFFFu, sq, off);
        if (lane == 0)
            acc += sqrtf(sq) * sS[kbase + m];
    }

    if (lane == 0) warp_sums[w] = acc;
    __syncthreads();

    if (tid == 0) {
        float s = 0.0f;
        #pragma unroll
        for (int i = 0; i < NWARPS; i++) s += warp_sums[i];
        atomicAdd(out, s);
    }
}

extern "C" void kernel_launch(void* const* d_in, const int* in_sizes, int n_in,
                              void* d_out, int out_size) {
    const float* P  = (const float*)d_in[0];
    const int*   ii = (const int*)  d_in[1];
    const int*   jj = (const int*)  d_in[2];
    const float* S  = (const float*)d_in[3];
    float* out = (float*)d_out;

    zero_out_kernel<<<1, 1>>>(out);
    custom_loss_kernel<<<B_TOTAL, NWARPS * 32>>>(P, ii, jj, S, out);
}

// round 3
// speedup vs baseline: 1.3117x; 1.2373x over previous
#include <cuda_runtime.h>

// penalty = sum_{b,k} S[b,k] * || P[i_b] - P[j_{b,k}] ||_2
// P [500000,128] f32, i [4096] i32, j [4096,64] i32, S [4096,64] f32 -> scalar f32.
// One warp per b; rolling 8-deep gather pipeline keeps DRAM busy continuously.

#define B_TOTAL 4096
#define K_NEIGH 64
#define D_DIM   128
#define WPB     4          // warps per block
#define WIN     8          // rolling gather window per warp

__global__ void zero_out_kernel(float* out) { *out = 0.0f; }

__global__ __launch_bounds__(WPB * 32, 8)
void custom_loss_kernel(const float* __restrict__ P,
                        const int*   __restrict__ i_idx,
                        const int*   __restrict__ j_idx,
                        const float* __restrict__ S,
                        float* __restrict__ out) {
    const int lane = threadIdx.x & 31;
    const int w    = threadIdx.x >> 5;
    const int b    = blockIdx.x * WPB + w;

    __shared__ int   sJ[WPB][K_NEIGH];
    __shared__ float sS[WPB][K_NEIGH];

    // Warp-private staging (coalesced), no block barrier needed.
    sJ[w][lane]      = j_idx[b * K_NEIGH + lane];
    sJ[w][32 + lane] = j_idx[b * K_NEIGH + 32 + lane];
    sS[w][lane]      = S[b * K_NEIGH + lane];
    sS[w][32 + lane] = S[b * K_NEIGH + 32 + lane];
    const long long irow = (long long)i_idx[b];
    const float4 pi = __ldg(reinterpret_cast<const float4*>(P + irow * D_DIM) + lane);
    __syncwarp();

    // Prologue: fill the gather window.
    float4 pj[WIN];
    #pragma unroll
    for (int m = 0; m < WIN; m++) {
        long long jr = (long long)sJ[w][m];
        pj[m] = __ldg(reinterpret_cast<const float4*>(P + jr * D_DIM) + lane);
    }

    float acc = 0.0f;
    for (int k0 = 0; k0 < K_NEIGH; k0 += WIN) {
        #pragma unroll
        for (int m = 0; m < WIN; m++) {
            const int k = k0 + m;
            // Consume slot m.
            float dx = pi.x - pj[m].x;
            float dy = pi.y - pj[m].y;
            float dz = pi.z - pj[m].z;
            float dw = pi.w - pj[m].w;
            // Refill slot m immediately (keeps ~WIN loads in flight).
            if (k + WIN < K_NEIGH) {
                long long jr = (long long)sJ[w][k + WIN];
                pj[m] = __ldg(reinterpret_cast<const float4*>(P + jr * D_DIM) + lane);
            }
            float sq = dx * dx + dy * dy + dz * dz + dw * dw;
            #pragma unroll
            for (int off = 16; off > 0; off >>= 1)
                sq += __shfl_xor_sync(0xFFFFFFFFu, sq, off);
            if (lane == 0)
                acc += sqrtf(sq) * sS[w][k];
        }
    }

    if (lane == 0) atomicAdd(out, acc);
}

extern "C" void kernel_launch(void* const* d_in, const int* in_sizes, int n_in,
                              void* d_out, int out_size) {
    const float* P  = (const float*)d_in[0];
    const int*   ii = (const int*)  d_in[1];
    const int*   jj = (const int*)  d_in[2];
    const float* S  = (const float*)d_in[3];
    float* out = (float*)d_out;

    zero_out_kernel<<<1, 1>>>(out);
    custom_loss_kernel<<<B_TOTAL / WPB, WPB * 32>>>(P, ii, jj, S, out);
}